// round 1
// baseline (speedup 1.0000x reference)
#include <cuda_runtime.h>

// FlowComposite: flows [B,T,2,H,W] fp32 -> out [B,2,H,W] fp32.
// Per-pixel independent chain over T: (u,v) += bilinear(flows[:,t], x+u-0.5, y+v-0.5)
// with zeros padding (grid_sample align_corners=False semantics).

static constexpr int Bc = 8;
static constexpr int Tc = 12;
static constexpr int Hc = 544;
static constexpr int Wc = 960;

__global__ __launch_bounds__(256)
void flow_composite_kernel(const float* __restrict__ flows, float* __restrict__ out) {
    const int HW = Hc * Wc;
    int idx = blockIdx.x * blockDim.x + threadIdx.x;
    if (idx >= Bc * HW) return;

    const int b = idx / HW;
    const int p = idx - b * HW;
    const int y = p / Wc;
    const int x = p - y * Wc;

    float u = 0.0f, v = 0.0f;
    const float* fb = flows + (size_t)b * Tc * 2 * HW;

    #pragma unroll
    for (int t = 0; t < Tc; ++t) {
        const float* f0 = fb + (size_t)t * 2 * HW;   // channel u
        const float* f1 = f0 + HW;                    // channel v

        const float px = (float)x + u - 0.5f;
        const float py = (float)y + v - 0.5f;

        const float x0f = floorf(px);
        const float y0f = floorf(py);
        const int x0 = (int)x0f;
        const int y0 = (int)y0f;

        const float wx1 = px - x0f;
        const float wy1 = py - y0f;
        const float wx0 = 1.0f - wx1;
        const float wy0 = 1.0f - wy1;

        const bool vx0 = (x0 >= 0) && (x0 <= Wc - 1);
        const bool vx1 = (x0 + 1 >= 0) && (x0 + 1 <= Wc - 1);
        const bool vy0 = (y0 >= 0) && (y0 <= Hc - 1);
        const bool vy1 = (y0 + 1 >= 0) && (y0 + 1 <= Hc - 1);

        const int xc0 = min(max(x0, 0), Wc - 1);
        const int xc1 = min(max(x0 + 1, 0), Wc - 1);
        const int yc0 = min(max(y0, 0), Hc - 1);
        const int yc1 = min(max(y0 + 1, 0), Hc - 1);

        const float w00 = wx0 * wy0 * ((vx0 && vy0) ? 1.0f : 0.0f);
        const float w10 = wx1 * wy0 * ((vx1 && vy0) ? 1.0f : 0.0f);
        const float w01 = wx0 * wy1 * ((vx0 && vy1) ? 1.0f : 0.0f);
        const float w11 = wx1 * wy1 * ((vx1 && vy1) ? 1.0f : 0.0f);

        const int i00 = yc0 * Wc + xc0;
        const int i10 = yc0 * Wc + xc1;
        const int i01 = yc1 * Wc + xc0;
        const int i11 = yc1 * Wc + xc1;

        // 8 independent loads -> good MLP; __ldg for read-only path.
        const float a00 = __ldg(f0 + i00);
        const float a10 = __ldg(f0 + i10);
        const float a01 = __ldg(f0 + i01);
        const float a11 = __ldg(f0 + i11);
        const float b00 = __ldg(f1 + i00);
        const float b10 = __ldg(f1 + i10);
        const float b01 = __ldg(f1 + i01);
        const float b11 = __ldg(f1 + i11);

        // Same summation order as reference: ((c00 + c10) + c01) + c11
        const float s0 = ((w00 * a00 + w10 * a10) + w01 * a01) + w11 * a11;
        const float s1 = ((w00 * b00 + w10 * b10) + w01 * b01) + w11 * b11;

        u += s0;
        v += s1;
    }

    float* ob = out + (size_t)b * 2 * HW;
    ob[p]      = u;
    ob[HW + p] = v;
}

extern "C" void kernel_launch(void* const* d_in, const int* in_sizes, int n_in,
                              void* d_out, int out_size) {
    const float* flows = (const float*)d_in[0];
    float* out = (float*)d_out;

    const int total = Bc * Hc * Wc;   // 4,177,920 threads
    const int threads = 256;
    const int blocks = (total + threads - 1) / threads;
    flow_composite_kernel<<<blocks, threads>>>(flows, out);
}

// round 2
// speedup vs baseline: 1.0149x; 1.0149x over previous
#include <cuda_runtime.h>

// FlowComposite: flows [B,T,2,H,W] fp32 -> out [B,2,H,W] fp32.
// Per-pixel independent chain over T: (u,v) += bilinear(flows[:,t], x+u-0.5, y+v-0.5)
// with zeros padding (grid_sample align_corners=False semantics).
//
// R2: 2D block tiling (64x4) so vertically adjacent pixel rows share gather
// lines in one SM's L1 (was: 1D row-slices -> every flow line fetched ~2x via L2).

static constexpr int Bc = 8;
static constexpr int Tc = 12;
static constexpr int Hc = 544;
static constexpr int Wc = 960;
static constexpr int HW = Hc * Wc;

// Block = 64 x 4 pixels (256 threads). Grid = (960/64, 544/4, 8) -> exact, no tails.
__global__ __launch_bounds__(256)
void flow_composite_kernel(const float* __restrict__ flows, float* __restrict__ out) {
    const int x = (blockIdx.x << 6) + (threadIdx.x & 63);
    const int y = (blockIdx.y << 2) + (threadIdx.x >> 6);
    const int b = blockIdx.z;

    const float xf = (float)x;
    const float yf = (float)y;

    float u = 0.0f, v = 0.0f;
    const float* fb = flows + (unsigned)b * (Tc * 2 * HW);

    #pragma unroll
    for (int t = 0; t < Tc; ++t) {
        const float* f0 = fb + (unsigned)t * (2 * HW);   // channel u plane
        const float* f1 = f0 + HW;                       // channel v plane

        const float px = xf + u - 0.5f;
        const float py = yf + v - 0.5f;

        const int x0 = __float2int_rd(px);
        const int y0 = __float2int_rd(py);

        const float wx1 = px - (float)x0;
        const float wy1 = py - (float)y0;
        const float wx0 = 1.0f - wx1;
        const float wy0 = 1.0f - wy1;

        const bool vx0 = (x0 >= 0) && (x0 <= Wc - 1);
        const bool vx1 = (x0 >= -1) && (x0 <= Wc - 2);
        const bool vy0 = (y0 >= 0) && (y0 <= Hc - 1);
        const bool vy1 = (y0 >= -1) && (y0 <= Hc - 2);

        const int xc0 = min(max(x0, 0), Wc - 1);
        const int xc1 = min(max(x0 + 1, 0), Wc - 1);
        const int yc0 = min(max(y0, 0), Hc - 1);
        const int yc1 = min(max(y0 + 1, 0), Hc - 1);

        const float w00 = wx0 * wy0 * ((vx0 && vy0) ? 1.0f : 0.0f);
        const float w10 = wx1 * wy0 * ((vx1 && vy0) ? 1.0f : 0.0f);
        const float w01 = wx0 * wy1 * ((vx0 && vy1) ? 1.0f : 0.0f);
        const float w11 = wx1 * wy1 * ((vx1 && vy1) ? 1.0f : 0.0f);

        const int r0 = yc0 * Wc;
        const int r1 = yc1 * Wc;
        const int i00 = r0 + xc0;
        const int i10 = r0 + xc1;
        const int i01 = r1 + xc0;
        const int i11 = r1 + xc1;

        // 8 independent gathers -> MLP 8; latency hidden by occupancy.
        const float a00 = __ldg(f0 + i00);
        const float a10 = __ldg(f0 + i10);
        const float a01 = __ldg(f0 + i01);
        const float a11 = __ldg(f0 + i11);
        const float b00 = __ldg(f1 + i00);
        const float b10 = __ldg(f1 + i10);
        const float b01 = __ldg(f1 + i01);
        const float b11 = __ldg(f1 + i11);

        // Same summation order as reference: ((c00 + c10) + c01) + c11
        const float s0 = ((w00 * a00 + w10 * a10) + w01 * a01) + w11 * a11;
        const float s1 = ((w00 * b00 + w10 * b10) + w01 * b01) + w11 * b11;

        u += s0;
        v += s1;
    }

    const int p = y * Wc + x;
    float* ob = out + (unsigned)b * (2 * HW);
    ob[p]      = u;
    ob[HW + p] = v;
}

extern "C" void kernel_launch(void* const* d_in, const int* in_sizes, int n_in,
                              void* d_out, int out_size) {
    const float* flows = (const float*)d_in[0];
    float* out = (float*)d_out;

    dim3 grid(Wc / 64, Hc / 4, Bc);   // 15 x 136 x 8, exact cover
    dim3 block(256);
    flow_composite_kernel<<<grid, block>>>(flows, out);
}